// round 14
// baseline (speedup 1.0000x reference)
#include <cuda_runtime.h>
#include <cstdint>

#define B_ROWS      8192
#define FEATURE_NUM 200
#define NUMERIC_SZ  100
#define IN_W        (FEATURE_NUM + NUMERIC_SZ)   // 300
#define EMBED       64
#define ROWS_PB     8                             // one warp per row
#define NTHREADS    (32 * ROWS_PB)                // 256
#define NBINS       64                            // id >> 14
#define HOT_IDS     380000                        // ~97MB pinned in L2
#define CH          8                             // ids per pipeline stage
#define NSTAGES     (FEATURE_NUM / CH)            // 25
#define STAGE_B     (CH * EMBED * 4)              // 2048 bytes

__device__ __forceinline__ float ldg_pol(const float* p, unsigned long long pol)
{
    float v;
    asm volatile("ld.global.nc.L2::cache_hint.f32 %0, [%1], %2;"
                 : "=f"(v) : "l"(p), "l"(pol));
    return v;
}

__global__ __launch_bounds__(NTHREADS)
void fm_kernel(const float* __restrict__ inputs,
               const float* __restrict__ w_one_hot,
               const float* __restrict__ w_numeric,
               const float* __restrict__ v_one_hot,
               const float* __restrict__ v_numeric,
               const float* __restrict__ bias,
               float* __restrict__ out)
{
    __shared__ int   s_sorted[ROWS_PB][FEATURE_NUM];
    __shared__ float s_num[ROWS_PB][NUMERIC_SZ];
    __shared__ int   s_bin[ROWS_PB][NBINS];
    __shared__ __align__(16) char s_buf[ROWS_PB][2][STAGE_B];   // 32 KB

    unsigned long long pol_last, pol_first;
    asm("createpolicy.fractional.L2::evict_last.b64 %0, 1.0;"  : "=l"(pol_last));
    asm("createpolicy.fractional.L2::evict_first.b64 %0, 1.0;" : "=l"(pol_first));

    const int tid  = threadIdx.x;
    const int lane = tid & 31;
    const int r    = tid >> 5;
    const int row  = blockIdx.x * ROWS_PB + r;
    const float* in_row = inputs + (long)row * IN_W;

    // ---- per-warp: zero bins, load ids to regs, histogram ----
    s_bin[r][lane] = 0;  s_bin[r][lane + 32] = 0;
    __syncwarp();

    int my_id[7];
    #pragma unroll
    for (int k = 0; k < 7; k++) {
        int j = lane + k * 32;
        my_id[k] = (j < FEATURE_NUM) ? (int)in_row[j] : -1;
        if (my_id[k] >= 0) atomicAdd(&s_bin[r][my_id[k] >> 14], 1);
    }
    // numeric features (warp-local staging)
    #pragma unroll
    for (int k = lane; k < NUMERIC_SZ; k += 32)
        s_num[r][k] = in_row[FEATURE_NUM + k];
    __syncwarp();

    // ---- warp-parallel exclusive prefix over 64 bins ----
    {
        int c0 = s_bin[r][lane], c1 = s_bin[r][lane + 32];
        int i0 = c0, i1 = c1;
        #pragma unroll
        for (int off = 1; off < 32; off <<= 1) {
            int t0 = __shfl_up_sync(0xffffffffu, i0, off);
            int t1 = __shfl_up_sync(0xffffffffu, i1, off);
            if (lane >= off) { i0 += t0; i1 += t1; }
        }
        int tot0 = __shfl_sync(0xffffffffu, i0, 31);
        i1 += tot0;
        s_bin[r][lane]      = i0 - c0;
        s_bin[r][lane + 32] = i1 - c1;
    }
    __syncwarp();

    // ---- scatter into ascending-bin order (approximate sort) ----
    #pragma unroll
    for (int k = 0; k < 7; k++)
        if (my_id[k] >= 0) {
            int pos = atomicAdd(&s_bin[r][my_id[k] >> 14], 1);
            s_sorted[r][pos] = my_id[k];
        }
    __syncwarp();

    // ---- first-order sparse part, issued EARLY so its L2 latency overlaps
    //      the cp.async gather pipeline below (ids already in registers) ----
    float fo = 0.f;
    #pragma unroll
    for (int k = 0; k < 7; k++)
        if (my_id[k] >= 0)
            fo += ldg_pol(&w_one_hot[my_id[k]], pol_last);

    // ---- cp.async pipelined gather: register-free MLP, 2KB stages ----
    const unsigned int buf0 =
        (unsigned int)__cvta_generic_to_shared(&s_buf[r][0][0]);

    auto issue_stage = [&](int st, int slot) {
        unsigned int dst = buf0 + slot * STAGE_B;
        #pragma unroll
        for (int t = 0; t < 4; t++) {
            int c  = lane + t * 32;                  // 0..127 : 16B chunk
            int id = s_sorted[r][st * CH + (c >> 4)];
            const char* src = (const char*)(v_one_hot + (long)id * EMBED)
                            + (c & 15) * 16;
            unsigned long long pol = (id < HOT_IDS) ? pol_last : pol_first;
            asm volatile("cp.async.cg.shared.global.L2::cache_hint [%0], [%1], 16, %2;"
                         :: "r"(dst + c * 16), "l"(src), "l"(pol) : "memory");
        }
        asm volatile("cp.async.commit_group;" ::: "memory");
    };

    float2 s  = make_float2(0.f, 0.f);
    float2 ss = make_float2(0.f, 0.f);

    issue_stage(0, 0);
    issue_stage(1, 1);

    #pragma unroll 1
    for (int st = 0; st < NSTAGES; st++) {
        if (st + 2 < NSTAGES)
            asm volatile("cp.async.wait_group 1;" ::: "memory");
        else
            asm volatile("cp.async.wait_group 0;" ::: "memory");
        __syncwarp();

        const float2* bp = (const float2*)&s_buf[r][st & 1][0];
        #pragma unroll
        for (int i = 0; i < CH; i++) {
            float2 v = bp[i * 32 + lane];            // columns 2*lane, 2*lane+1
            s.x += v.x;  s.y += v.y;
            ss.x = fmaf(v.x, v.x, ss.x);
            ss.y = fmaf(v.y, v.y, ss.y);
        }
        __syncwarp();
        if (st + 2 < NSTAGES) issue_stage(st + 2, st & 1);
    }

    // ---- dense numeric part ----
    const int c0 = lane * 2;
    #pragma unroll 4
    for (int k = 0; k < NUMERIC_SZ; k++) {
        float  n  = s_num[r][k];
        float2 vn = *(const float2*)&v_numeric[k * EMBED + c0];
        float tx = n * vn.x, ty = n * vn.y;
        s.x += tx;  s.y += ty;
        ss.x = fmaf(tx, tx, ss.x);
        ss.y = fmaf(ty, ty, ss.y);
    }
    #pragma unroll
    for (int k = lane; k < NUMERIC_SZ; k += 32)
        fo = fmaf(s_num[r][k], __ldg(&w_numeric[k]), fo);

    // ---- combine + warp reduce ----
    float so  = fmaf(s.x, s.x, -ss.x) + fmaf(s.y, s.y, -ss.y);
    float val = fmaf(0.5f, so, fo);

    #pragma unroll
    for (int off = 16; off > 0; off >>= 1)
        val += __shfl_xor_sync(0xffffffffu, val, off);

    if (lane == 0)
        out[row] = val + bias[0];
}

extern "C" void kernel_launch(void* const* d_in, const int* in_sizes, int n_in,
                              void* d_out, int out_size)
{
    const float* inputs    = (const float*)d_in[0];
    const float* w_one_hot = (const float*)d_in[1];
    const float* w_numeric = (const float*)d_in[2];
    const float* v_one_hot = (const float*)d_in[3];
    const float* v_numeric = (const float*)d_in[4];
    const float* bias      = (const float*)d_in[5];
    float* out = (float*)d_out;

    fm_kernel<<<B_ROWS / ROWS_PB, NTHREADS>>>(inputs, w_one_hot, w_numeric,
                                              v_one_hot, v_numeric, bias, out);
}

// round 15
// speedup vs baseline: 1.0557x; 1.0557x over previous
#include <cuda_runtime.h>
#include <cstdint>

#define B_ROWS      8192
#define FEATURE_NUM 200
#define NUMERIC_SZ  100
#define IN_W        (FEATURE_NUM + NUMERIC_SZ)   // 300
#define EMBED       64
#define ROWS_PB     8                             // one warp per row
#define NTHREADS    (32 * ROWS_PB)                // 256
#define NBINS       64                            // id >> 14
#define HOT_IDS     380000                        // ~97MB pinned in L2
#define CH          4                             // ids per pipeline stage
#define NSTAGES     (FEATURE_NUM / CH)            // 50
#define STAGE_B     (CH * EMBED * 4)              // 1024 bytes

__device__ __forceinline__ float ldg_pol(const float* p, unsigned long long pol)
{
    float v;
    asm volatile("ld.global.nc.L2::cache_hint.f32 %0, [%1], %2;"
                 : "=f"(v) : "l"(p), "l"(pol));
    return v;
}

__global__ __launch_bounds__(NTHREADS)
void fm_kernel(const float* __restrict__ inputs,
               const float* __restrict__ w_one_hot,
               const float* __restrict__ w_numeric,
               const float* __restrict__ v_one_hot,
               const float* __restrict__ v_numeric,
               const float* __restrict__ bias,
               float* __restrict__ out)
{
    __shared__ int   s_sorted[ROWS_PB][FEATURE_NUM];
    __shared__ float s_num[ROWS_PB][NUMERIC_SZ];
    __shared__ int   s_bin[ROWS_PB][NBINS];
    __shared__ __align__(16) char s_buf[ROWS_PB][2][STAGE_B];

    unsigned long long pol_last, pol_first;
    asm("createpolicy.fractional.L2::evict_last.b64 %0, 1.0;"  : "=l"(pol_last));
    asm("createpolicy.fractional.L2::evict_first.b64 %0, 1.0;" : "=l"(pol_first));

    const int tid  = threadIdx.x;
    const int lane = tid & 31;
    const int r    = tid >> 5;
    const int row  = blockIdx.x * ROWS_PB + r;
    const float* in_row = inputs + (long)row * IN_W;

    // ---- per-warp: zero bins, load ids to regs, histogram ----
    s_bin[r][lane] = 0;  s_bin[r][lane + 32] = 0;
    __syncwarp();

    int my_id[7];
    #pragma unroll
    for (int k = 0; k < 7; k++) {
        int j = lane + k * 32;
        my_id[k] = (j < FEATURE_NUM) ? (int)in_row[j] : -1;
        if (my_id[k] >= 0) atomicAdd(&s_bin[r][my_id[k] >> 14], 1);
    }
    // numeric features (warp-local staging)
    #pragma unroll
    for (int k = lane; k < NUMERIC_SZ; k += 32)
        s_num[r][k] = in_row[FEATURE_NUM + k];
    __syncwarp();

    // ---- warp-parallel exclusive prefix over 64 bins ----
    {
        int c0 = s_bin[r][lane], c1 = s_bin[r][lane + 32];
        int i0 = c0, i1 = c1;
        #pragma unroll
        for (int off = 1; off < 32; off <<= 1) {
            int t0 = __shfl_up_sync(0xffffffffu, i0, off);
            int t1 = __shfl_up_sync(0xffffffffu, i1, off);
            if (lane >= off) { i0 += t0; i1 += t1; }
        }
        int tot0 = __shfl_sync(0xffffffffu, i0, 31);
        i1 += tot0;
        s_bin[r][lane]      = i0 - c0;
        s_bin[r][lane + 32] = i1 - c1;
    }
    __syncwarp();

    // ---- scatter into ascending-bin order (approximate sort) ----
    #pragma unroll
    for (int k = 0; k < 7; k++)
        if (my_id[k] >= 0) {
            int pos = atomicAdd(&s_bin[r][my_id[k] >> 14], 1);
            s_sorted[r][pos] = my_id[k];
        }
    __syncwarp();

    // ---- first-order sparse part, issued EARLY so its L2 latency overlaps
    //      the cp.async gather pipeline below (ids already in registers) ----
    float fo = 0.f;
    #pragma unroll
    for (int k = 0; k < 7; k++)
        if (my_id[k] >= 0)
            fo += ldg_pol(&w_one_hot[my_id[k]], pol_last);

    // ---- cp.async pipelined gather: register-free MLP ----
    const unsigned int buf0 =
        (unsigned int)__cvta_generic_to_shared(&s_buf[r][0][0]);

    auto issue_stage = [&](int st, int slot) {
        unsigned int dst = buf0 + slot * STAGE_B;
        #pragma unroll
        for (int t = 0; t < 2; t++) {
            int c  = lane + t * 32;                  // 0..63 : 16B chunk
            int id = s_sorted[r][st * CH + (c >> 4)];
            const char* src = (const char*)(v_one_hot + (long)id * EMBED)
                            + (c & 15) * 16;
            unsigned long long pol = (id < HOT_IDS) ? pol_last : pol_first;
            asm volatile("cp.async.cg.shared.global.L2::cache_hint [%0], [%1], 16, %2;"
                         :: "r"(dst + c * 16), "l"(src), "l"(pol) : "memory");
        }
        asm volatile("cp.async.commit_group;" ::: "memory");
    };

    float2 s  = make_float2(0.f, 0.f);
    float2 ss = make_float2(0.f, 0.f);

    issue_stage(0, 0);
    issue_stage(1, 1);

    #pragma unroll 1
    for (int st = 0; st < NSTAGES; st++) {
        if (st + 2 < NSTAGES)
            asm volatile("cp.async.wait_group 1;" ::: "memory");
        else
            asm volatile("cp.async.wait_group 0;" ::: "memory");
        __syncwarp();

        const float2* bp = (const float2*)&s_buf[r][st & 1][0];
        #pragma unroll
        for (int i = 0; i < CH; i++) {
            float2 v = bp[i * 32 + lane];            // columns 2*lane, 2*lane+1
            s.x += v.x;  s.y += v.y;
            ss.x = fmaf(v.x, v.x, ss.x);
            ss.y = fmaf(v.y, v.y, ss.y);
        }
        __syncwarp();
        if (st + 2 < NSTAGES) issue_stage(st + 2, st & 1);
    }

    // ---- dense numeric part ----
    const int c0 = lane * 2;
    #pragma unroll 4
    for (int k = 0; k < NUMERIC_SZ; k++) {
        float  n  = s_num[r][k];
        float2 vn = *(const float2*)&v_numeric[k * EMBED + c0];
        float tx = n * vn.x, ty = n * vn.y;
        s.x += tx;  s.y += ty;
        ss.x = fmaf(tx, tx, ss.x);
        ss.y = fmaf(ty, ty, ss.y);
    }
    #pragma unroll
    for (int k = lane; k < NUMERIC_SZ; k += 32)
        fo = fmaf(s_num[r][k], __ldg(&w_numeric[k]), fo);

    // ---- combine + warp reduce ----
    float so  = fmaf(s.x, s.x, -ss.x) + fmaf(s.y, s.y, -ss.y);
    float val = fmaf(0.5f, so, fo);

    #pragma unroll
    for (int off = 16; off > 0; off >>= 1)
        val += __shfl_xor_sync(0xffffffffu, val, off);

    if (lane == 0)
        out[row] = val + bias[0];
}

extern "C" void kernel_launch(void* const* d_in, const int* in_sizes, int n_in,
                              void* d_out, int out_size)
{
    const float* inputs    = (const float*)d_in[0];
    const float* w_one_hot = (const float*)d_in[1];
    const float* w_numeric = (const float*)d_in[2];
    const float* v_one_hot = (const float*)d_in[3];
    const float* v_numeric = (const float*)d_in[4];
    const float* bias      = (const float*)d_in[5];
    float* out = (float*)d_out;

    fm_kernel<<<B_ROWS / ROWS_PB, NTHREADS>>>(inputs, w_one_hot, w_numeric,
                                              v_one_hot, v_numeric, bias, out);
}

// round 16
// speedup vs baseline: 1.0874x; 1.0301x over previous
#include <cuda_runtime.h>
#include <cstdint>

#define B_ROWS      8192
#define FEATURE_NUM 200
#define NUMERIC_SZ  100
#define IN_W        (FEATURE_NUM + NUMERIC_SZ)   // 300
#define EMBED       64
#define ROWS_PB     8                             // one warp per row
#define NTHREADS    (32 * ROWS_PB)                // 256
#define NBINS       64                            // id >> 14
#define HOT_IDS     380000                        // ~97MB pinned in L2
#define CH          4                             // ids per pipeline stage
#define NSTAGES     (FEATURE_NUM / CH)            // 50
#define STAGE_B     (CH * EMBED * 4)              // 1024 bytes

__device__ __forceinline__ float ldg_pol(const float* p, unsigned long long pol)
{
    float v;
    asm volatile("ld.global.nc.L2::cache_hint.f32 %0, [%1], %2;"
                 : "=f"(v) : "l"(p), "l"(pol));
    return v;
}

__global__ __launch_bounds__(NTHREADS)
void fm_kernel(const float* __restrict__ inputs,
               const float* __restrict__ w_one_hot,
               const float* __restrict__ w_numeric,
               const float* __restrict__ v_one_hot,
               const float* __restrict__ v_numeric,
               const float* __restrict__ bias,
               float* __restrict__ out)
{
    __shared__ int   s_sorted[ROWS_PB][FEATURE_NUM];
    __shared__ float s_num[ROWS_PB][NUMERIC_SZ];
    __shared__ int   s_bin[ROWS_PB][NBINS];
    __shared__ __align__(16) char s_buf[ROWS_PB][2][STAGE_B];

    unsigned long long pol_last, pol_first;
    asm("createpolicy.fractional.L2::evict_last.b64 %0, 1.0;"  : "=l"(pol_last));
    asm("createpolicy.fractional.L2::evict_first.b64 %0, 1.0;" : "=l"(pol_first));

    const int tid  = threadIdx.x;
    const int lane = tid & 31;
    const int r    = tid >> 5;
    const int row  = blockIdx.x * ROWS_PB + r;
    const float* in_row = inputs + (long)row * IN_W;

    // ---- per-warp: zero bins, load ids to regs, histogram ----
    s_bin[r][lane] = 0;  s_bin[r][lane + 32] = 0;
    __syncwarp();

    int my_id[7];
    #pragma unroll
    for (int k = 0; k < 7; k++) {
        int j = lane + k * 32;
        my_id[k] = (j < FEATURE_NUM) ? (int)in_row[j] : -1;
        if (my_id[k] >= 0) atomicAdd(&s_bin[r][my_id[k] >> 14], 1);
    }
    // numeric features (warp-local staging)
    #pragma unroll
    for (int k = lane; k < NUMERIC_SZ; k += 32)
        s_num[r][k] = in_row[FEATURE_NUM + k];
    __syncwarp();

    // ---- warp-parallel exclusive prefix over 64 bins ----
    {
        int c0 = s_bin[r][lane], c1 = s_bin[r][lane + 32];
        int i0 = c0, i1 = c1;
        #pragma unroll
        for (int off = 1; off < 32; off <<= 1) {
            int t0 = __shfl_up_sync(0xffffffffu, i0, off);
            int t1 = __shfl_up_sync(0xffffffffu, i1, off);
            if (lane >= off) { i0 += t0; i1 += t1; }
        }
        int tot0 = __shfl_sync(0xffffffffu, i0, 31);
        i1 += tot0;
        s_bin[r][lane]      = i0 - c0;
        s_bin[r][lane + 32] = i1 - c1;
    }
    __syncwarp();

    // ---- scatter into ascending-bin order (approximate sort) ----
    #pragma unroll
    for (int k = 0; k < 7; k++)
        if (my_id[k] >= 0) {
            int pos = atomicAdd(&s_bin[r][my_id[k] >> 14], 1);
            s_sorted[r][pos] = my_id[k];
        }
    __syncwarp();

    // ---- first-order sparse part, issued EARLY so its L2 latency overlaps
    //      the cp.async gather pipeline below (ids already in registers) ----
    float fo = 0.f;
    #pragma unroll
    for (int k = 0; k < 7; k++)
        if (my_id[k] >= 0)
            fo += ldg_pol(&w_one_hot[my_id[k]], pol_last);

    // ---- cp.async pipelined gather: register-free MLP ----
    const unsigned int buf0 =
        (unsigned int)__cvta_generic_to_shared(&s_buf[r][0][0]);

    auto issue_stage = [&](int st, int slot) {
        unsigned int dst = buf0 + slot * STAGE_B;
        #pragma unroll
        for (int t = 0; t < 2; t++) {
            int c  = lane + t * 32;                  // 0..63 : 16B chunk
            int id = s_sorted[r][st * CH + (c >> 4)];
            const char* src = (const char*)(v_one_hot + (long)id * EMBED)
                            + (c & 15) * 16;
            unsigned long long pol = (id < HOT_IDS) ? pol_last : pol_first;
            asm volatile("cp.async.cg.shared.global.L2::cache_hint [%0], [%1], 16, %2;"
                         :: "r"(dst + c * 16), "l"(src), "l"(pol) : "memory");
        }
        asm volatile("cp.async.commit_group;" ::: "memory");
    };

    float2 s  = make_float2(0.f, 0.f);
    float2 ss = make_float2(0.f, 0.f);

    issue_stage(0, 0);
    issue_stage(1, 1);

    #pragma unroll 1
    for (int st = 0; st < NSTAGES; st++) {
        if (st + 2 < NSTAGES)
            asm volatile("cp.async.wait_group 1;" ::: "memory");
        else
            asm volatile("cp.async.wait_group 0;" ::: "memory");
        __syncwarp();

        const float2* bp = (const float2*)&s_buf[r][st & 1][0];
        #pragma unroll
        for (int i = 0; i < CH; i++) {
            float2 v = bp[i * 32 + lane];            // columns 2*lane, 2*lane+1
            s.x += v.x;  s.y += v.y;
            ss.x = fmaf(v.x, v.x, ss.x);
            ss.y = fmaf(v.y, v.y, ss.y);
        }
        __syncwarp();
        if (st + 2 < NSTAGES) issue_stage(st + 2, st & 1);
    }

    // ---- dense numeric part ----
    const int c0 = lane * 2;
    #pragma unroll 4
    for (int k = 0; k < NUMERIC_SZ; k++) {
        float  n  = s_num[r][k];
        float2 vn = *(const float2*)&v_numeric[k * EMBED + c0];
        float tx = n * vn.x, ty = n * vn.y;
        s.x += tx;  s.y += ty;
        ss.x = fmaf(tx, tx, ss.x);
        ss.y = fmaf(ty, ty, ss.y);
    }
    #pragma unroll
    for (int k = lane; k < NUMERIC_SZ; k += 32)
        fo = fmaf(s_num[r][k], __ldg(&w_numeric[k]), fo);

    // ---- combine + warp reduce ----
    float so  = fmaf(s.x, s.x, -ss.x) + fmaf(s.y, s.y, -ss.y);
    float val = fmaf(0.5f, so, fo);

    #pragma unroll
    for (int off = 16; off > 0; off >>= 1)
        val += __shfl_xor_sync(0xffffffffu, val, off);

    if (lane == 0)
        out[row] = val + bias[0];
}

extern "C" void kernel_launch(void* const* d_in, const int* in_sizes, int n_in,
                              void* d_out, int out_size)
{
    const float* inputs    = (const float*)d_in[0];
    const float* w_one_hot = (const float*)d_in[1];
    const float* w_numeric = (const float*)d_in[2];
    const float* v_one_hot = (const float*)d_in[3];
    const float* v_numeric = (const float*)d_in[4];
    const float* bias      = (const float*)d_in[5];
    float* out = (float*)d_out;

    fm_kernel<<<B_ROWS / ROWS_PB, NTHREADS>>>(inputs, w_one_hot, w_numeric,
                                              v_one_hot, v_numeric, bias, out);
}